// round 13
// baseline (speedup 1.0000x reference)
#include <cuda_runtime.h>
#include <cuda_fp16.h>

// Problem constants: N=100000, E=1600000, IN_C=16, HID=32, HEADS=2
#define MAXN 100000
#define MAXE 1600000
#define NEG 0.2f
#define INV_TEMP (1.0f / 0.7f)

// ---- device scratch (static; no allocations allowed; zero-init at load) ----
__device__ __align__(16) __half g_xp[MAXN * 64];   // [N][64] projected features (fp16)
__device__ float g_asrc[MAXN * 2];                 // attention src logits per head
__device__ float g_adst[MAXN * 2];                 // attention dst logits per head
__device__ __align__(16) __half g_ps[MAXN * 32];   // h @ w1[0:32,:]  (fp16)
__device__ __align__(16) __half g_pd[MAXN * 32];   // h @ w1[32:64,:] (fp16)
__device__ __align__(16) int2 g_edge[MAXE];        // packed (src, dst)
__device__ __align__(16) int g_rank[MAXE];         // rank of edge within its dst group
__device__ __align__(16) int g_srcs[MAXE];         // CSR: src ids grouped by dst
__device__ __align__(16) float2 g_w[MAXE];         // CSR: per-edge softmax weights (2 heads)
__device__ int g_deg[MAXN];                        // in-degree histogram (re-zeroed by scan)
__device__ int g_off[MAXN + 1];                    // CSR offsets
__device__ int g_bsum[128];                        // scan block totals
__device__ int g_bflag[128];                       // scan publish flags
__device__ int g_done;                             // scan->scatter barrier counter
__device__ int g_is64;

// K_init: zero scan flags + barrier counter; detect edge int width.
__global__ void k_init(const int* __restrict__ ei_words) {
    int t = threadIdx.x;
    g_bflag[t] = 0;
    if (t == 0) {
        g_done = 0;
        int nonzero = 0;
        #pragma unroll
        for (int j = 0; j < 64; j++)
            if (ei_words[2 * j + 1] != 0) nonzero++;
        g_is64 = (nonzero == 0) ? 1 : 0;
    }
}

// K_pack_node: blocks [0, nodeBlocks) do the node projection (chunked,
// low-reg); remaining blocks pack edges + histogram + per-dst rank.
__global__ void __launch_bounds__(256, 4) k_pack_node(
    const void* __restrict__ ei,
    const float* __restrict__ x, const float* __restrict__ W,
    const float* __restrict__ att_src, const float* __restrict__ att_dst,
    int N, int E, int nodeBlocks) {
    int tid = threadIdx.x;

    if (blockIdx.x >= (unsigned)nodeBlocks) {
        // ---- edge pack part ----
        int e = (blockIdx.x - nodeBlocks) * blockDim.x + tid;
        if (e >= E) return;
        int s, d;
        if (g_is64) {
            const long long* p = (const long long*)ei;
            s = (int)p[e];
            d = (int)p[e + E];
        } else {
            const int* p = (const int*)ei;
            s = p[e];
            d = p[e + E];
        }
        g_edge[e] = make_int2(s, d);
        g_rank[e] = atomicAdd(&g_deg[d], 1);
        return;
    }

    // ---- node projection part (chunked, 16 output columns at a time) ----
    __shared__ float sW[16 * 64];
    __shared__ float sAs[64];
    __shared__ float sAd[64];
    for (int i = tid; i < 16 * 64; i += blockDim.x) sW[i] = W[i];
    if (tid < 64) { sAs[tid] = att_src[tid]; sAd[tid] = att_dst[tid]; }
    __syncthreads();

    int n = blockIdx.x * blockDim.x + tid;
    if (n >= N) return;

    float xv[16];
    const float4* x4 = (const float4*)(x + (size_t)n * 16);
    #pragma unroll
    for (int i = 0; i < 4; i++) {
        float4 t = x4[i];
        xv[4 * i + 0] = t.x; xv[4 * i + 1] = t.y;
        xv[4 * i + 2] = t.z; xv[4 * i + 3] = t.w;
    }

    float hs[2] = {0.f, 0.f};
    float hd[2] = {0.f, 0.f};
    uint4* xpo = (uint4*)(g_xp + (size_t)n * 64);

    #pragma unroll
    for (int ch = 0; ch < 4; ch++) {
        float v[16];
        float as = 0.f, ad = 0.f;
        #pragma unroll
        for (int jj = 0; jj < 16; jj++) {
            int j = ch * 16 + jj;
            float acc = 0.f;
            #pragma unroll
            for (int k = 0; k < 16; k++) acc = fmaf(xv[k], sW[k * 64 + j], acc);
            v[jj] = acc;
            as = fmaf(sAs[j], acc, as);
            ad = fmaf(sAd[j], acc, ad);
        }
        int hh = ch >> 1;
        hs[hh] += as;
        hd[hh] += ad;
        union { uint4 u; __half2 p[4]; } pk;
        #pragma unroll
        for (int g = 0; g < 2; g++) {
            #pragma unroll
            for (int j = 0; j < 4; j++)
                pk.p[j] = __floats2half2_rn(v[8 * g + 2 * j], v[8 * g + 2 * j + 1]);
            xpo[2 * ch + g] = pk.u;
        }
    }

    g_asrc[n * 2 + 0] = hs[0]; g_asrc[n * 2 + 1] = hs[1];
    g_adst[n * 2 + 0] = hd[0]; g_adst[n * 2 + 1] = hd[1];
}

// K_scan_scatter: one kernel, two phases.
// Phase 1: exclusive scan of g_deg -> g_off (warp-shuffle block scan +
//   parallel lookback; 98 co-resident blocks). Re-zeroes g_deg.
// Barrier (same residency guarantee as lookback), then
// Phase 2: atomic-free scatter + per-edge softmax weight precompute:
//   pos = off[dst]+rank; g_srcs[pos]=src; g_w[pos]=exp(leaky(asrc+adst)) x2.
__global__ void __launch_bounds__(1024) k_scan_scatter(int N, int E, int NB) {
    __shared__ int warpsums[32];
    __shared__ int sred[32];
    __shared__ int sbase;
    const unsigned FULL = 0xFFFFFFFFu;
    int tid = threadIdx.x;
    int lane = tid & 31, wid = tid >> 5;
    int b = blockIdx.x;
    int i = b * 1024 + tid;

    // ---- phase 1: scan ----
    int v = (i < N) ? g_deg[i] : 0;
    if (i < N) g_deg[i] = 0;                 // restore invariant for next call
    int sc = v;
    #pragma unroll
    for (int ofs = 1; ofs < 32; ofs <<= 1) {
        int t = __shfl_up_sync(FULL, sc, ofs);
        if (lane >= ofs) sc += t;
    }
    if (lane == 31) warpsums[wid] = sc;
    __syncthreads();
    if (wid == 0) {
        int w = warpsums[lane];
        #pragma unroll
        for (int ofs = 1; ofs < 32; ofs <<= 1) {
            int t = __shfl_up_sync(FULL, w, ofs);
            if (lane >= ofs) w += t;
        }
        warpsums[lane] = w;
    }
    __syncthreads();
    int blockpref = (wid > 0) ? warpsums[wid - 1] : 0;
    int excl = sc + blockpref - v;
    int total = warpsums[31];

    if (tid == 0) {
        g_bsum[b] = total;
        __threadfence();
        atomicExch(&g_bflag[b], 1);
    }

    int part = 0;
    if (tid < b) {
        while (atomicAdd(&g_bflag[tid], 0) == 0) { }
        __threadfence();
        part = g_bsum[tid];
    }
    #pragma unroll
    for (int ofs = 16; ofs > 0; ofs >>= 1)
        part += __shfl_xor_sync(FULL, part, ofs);
    if (lane == 0) sred[wid] = part;
    __syncthreads();
    if (tid == 0) {
        int s = 0;
        #pragma unroll
        for (int k = 0; k < 4; k++) s += sred[k];
        sbase = s;
    }
    __syncthreads();

    if (i < N) g_off[i] = excl + sbase;
    if (b == 0 && tid == 0) g_off[N] = E;

    // ---- device-wide barrier (all NB blocks co-resident) ----
    __threadfence();
    __syncthreads();
    if (tid == 0) atomicAdd(&g_done, 1);
    if (tid == 0) {
        while (atomicAdd(&g_done, 0) < NB) { }
    }
    __syncthreads();
    __threadfence();

    // ---- phase 2: scatter + weight precompute (grid-stride) ----
    int S = NB * 1024;
    for (int e = b * 1024 + tid; e < E; e += S) {
        int2 sd = g_edge[e];
        int r = g_rank[e];
        int o = __ldg(&g_off[sd.y]);
        float2 as = *(const float2*)(g_asrc + 2 * sd.x);
        float2 ad = *(const float2*)(g_adst + 2 * sd.y);
        float e0 = as.x + ad.x; e0 = e0 > 0.f ? e0 : NEG * e0;
        float e1 = as.y + ad.y; e1 = e1 > 0.f ? e1 : NEG * e1;
        int pos = o + r;
        g_srcs[pos] = sd.x;
        g_w[pos] = make_float2(__expf(e0), __expf(e1));
    }
}

// K2b3: warp-per-destination GAT aggregation + fused MLP layer-1 fold.
// Per-edge weights are PRECOMPUTED in CSR order (g_w) — the hot loop is just
// broadcast weight loads + the xp gather + FMAs. Lane c owns channels
// {2c, 2c+1}, head = c/16.
__global__ void __launch_bounds__(256) k2b3_aggregate(const float* __restrict__ bias,
                                                      const float* __restrict__ w1, int N) {
    __shared__ float sW1[64 * 32];
    int tid = threadIdx.x;
    for (int i = tid; i < 64 * 32; i += blockDim.x) sW1[i] = w1[i];
    __syncthreads();

    int n = (blockIdx.x * blockDim.x + tid) >> 5;
    if (n >= N) return;
    int c = tid & 31;
    int h = c >> 4;
    const unsigned FULL = 0xFFFFFFFFu;

    // self loop (computed once per node, cheap)
    float ee = g_asrc[n * 2 + h] + g_adst[n * 2 + h];
    ee = ee > 0.f ? ee : NEG * ee;
    float w = __expf(ee);
    float2 xs = __half22float2(*(const __half2*)(g_xp + (size_t)n * 64 + 2 * c));
    float acc0 = w * xs.x, acc1 = w * xs.y, dsum = w;

    int i = g_off[n];
    int end = g_off[n + 1];

    for (; i + 8 <= end; i += 8) {
        int s[8];
        float wv[8];
        __half2 xh[8];
        #pragma unroll
        for (int j = 0; j < 8; j++) {
            s[j] = __ldg(&g_srcs[i + j]);
            float2 wp = __ldg(&g_w[i + j]);
            wv[j] = h ? wp.y : wp.x;
        }
        #pragma unroll
        for (int j = 0; j < 8; j++)
            xh[j] = *(const __half2*)(g_xp + (size_t)s[j] * 64 + 2 * c);
        #pragma unroll
        for (int j = 0; j < 8; j++) {
            dsum += wv[j];
            float2 f = __half22float2(xh[j]);
            acc0 = fmaf(wv[j], f.x, acc0);
            acc1 = fmaf(wv[j], f.y, acc1);
        }
    }
    for (; i < end; i++) {
        int s = __ldg(&g_srcs[i]);
        float2 wp = __ldg(&g_w[i]);
        float w0 = h ? wp.y : wp.x;
        __half2 xh = *(const __half2*)(g_xp + (size_t)s * 64 + 2 * c);
        dsum += w0;
        float2 f = __half22float2(xh);
        acc0 = fmaf(w0, f.x, acc0);
        acc1 = fmaf(w0, f.y, acc1);
    }

    float d0 = __shfl_sync(FULL, dsum, 0);
    float d1 = __shfl_sync(FULL, dsum, 16);
    float p0 = __shfl_sync(FULL, acc0, (c + 16) & 31);
    float p1 = __shfl_sync(FULL, acc1, (c + 16) & 31);

    int c15 = c & 15;
    float h0 = 0.5f * (acc0 / d0 + p0 / d1) + __ldg(&bias[2 * c15]);
    float h1 = 0.5f * (acc1 / d0 + p1 / d1) + __ldg(&bias[2 * c15 + 1]);

    // fused k3: ps/pd = h @ w1 (lane c computes output channel c)
    float ps = 0.f, pd = 0.f;
    #pragma unroll
    for (int k = 0; k < 16; k++) {
        float ha = __shfl_sync(FULL, h0, k);
        float hb = __shfl_sync(FULL, h1, k);
        ps = fmaf(ha, sW1[(2 * k) * 32 + c], ps);
        ps = fmaf(hb, sW1[(2 * k + 1) * 32 + c], ps);
        pd = fmaf(ha, sW1[(32 + 2 * k) * 32 + c], pd);
        pd = fmaf(hb, sW1[(32 + 2 * k + 1) * 32 + c], pd);
    }
    g_ps[(size_t)n * 32 + c] = __float2half_rn(ps);
    g_pd[(size_t)n * 32 + c] = __float2half_rn(pd);
}

// K4: per-edge MLP. 4-lane group per consecutive edge pair (one int4 edge
// load); two independent pairs in flight per thread. ps+pd summed in half2.
__device__ __forceinline__ float mlp_quarter(const uint4 a, const uint4 b,
                                             const float* b1r, const float* w2r) {
    union { uint4 u; __half2 hh[4]; } ua, ub;
    ua.u = a; ub.u = b;
    float acc = 0.f;
    #pragma unroll
    for (int j = 0; j < 4; j++) {
        __half2 s = __hadd2(ua.hh[j], ub.hh[j]);
        float2 f = __half22float2(s);
        float h0 = fmaxf(f.x + b1r[2 * j], 0.f);
        float h1 = fmaxf(f.y + b1r[2 * j + 1], 0.f);
        acc = fmaf(h0, w2r[2 * j], acc);
        acc = fmaf(h1, w2r[2 * j + 1], acc);
    }
    return acc;
}

__global__ void __launch_bounds__(256) k4_edge_mlp(const float* __restrict__ b1,
                                                   const float* __restrict__ w2,
                                                   const float* __restrict__ b2,
                                                   float* __restrict__ out, int E) {
    int tid = blockIdx.x * blockDim.x + threadIdx.x;
    int q = tid & 3;
    float b1r[8], w2r[8];
    #pragma unroll
    for (int i = 0; i < 8; i++) {
        b1r[i] = __ldg(&b1[q * 8 + i]);
        w2r[i] = __ldg(&w2[q * 8 + i]);
    }
    float b2v = __ldg(&b2[0]);
    const unsigned FULL = 0xFFFFFFFFu;

    int nGroups = (gridDim.x * blockDim.x) >> 2;
    int nPairs = (E + 1) >> 1;

    for (int p = tid >> 2; p < nPairs; p += 2 * nGroups) {
        int pB = p + nGroups;
        bool hasB = pB < nPairs;
        int eA = 2 * p, eB = 2 * pB;

        int4 edA = __ldg((const int4*)(g_edge + eA));
        int4 edB = hasB ? __ldg((const int4*)(g_edge + eB)) : make_int4(0, 0, 0, 0);

        uint4 psA0 = *((const uint4*)(g_ps + (size_t)edA.x * 32) + q);
        uint4 pdA0 = *((const uint4*)(g_pd + (size_t)edA.y * 32) + q);
        uint4 psA1 = *((const uint4*)(g_ps + (size_t)edA.z * 32) + q);
        uint4 pdA1 = *((const uint4*)(g_pd + (size_t)edA.w * 32) + q);
        uint4 psB0 = *((const uint4*)(g_ps + (size_t)edB.x * 32) + q);
        uint4 pdB0 = *((const uint4*)(g_pd + (size_t)edB.y * 32) + q);
        uint4 psB1 = *((const uint4*)(g_ps + (size_t)edB.z * 32) + q);
        uint4 pdB1 = *((const uint4*)(g_pd + (size_t)edB.w * 32) + q);

        float vA0 = mlp_quarter(psA0, pdA0, b1r, w2r);
        float vA1 = mlp_quarter(psA1, pdA1, b1r, w2r);
        float vB0 = mlp_quarter(psB0, pdB0, b1r, w2r);
        float vB1 = mlp_quarter(psB1, pdB1, b1r, w2r);

        float a0 = vA0 + __shfl_xor_sync(FULL, vA0, 1);
        float a1 = vA1 + __shfl_xor_sync(FULL, vA1, 1);
        float mA = (q & 1) ? a1 : a0;
        mA += __shfl_xor_sync(FULL, mA, 2);

        float c0 = vB0 + __shfl_xor_sync(FULL, vB0, 1);
        float c1 = vB1 + __shfl_xor_sync(FULL, vB1, 1);
        float mB = (q & 1) ? c1 : c0;
        mB += __shfl_xor_sync(FULL, mB, 2);

        if (q < 2) {
            int e = eA + q;
            if (e < E) out[e] = (mA + b2v) * INV_TEMP;
            if (hasB) {
                int e2 = eB + q;
                if (e2 < E) out[e2] = (mB + b2v) * INV_TEMP;
            }
        }
    }
}

extern "C" void kernel_launch(void* const* d_in, const int* in_sizes, int n_in,
                              void* d_out, int out_size) {
    const float* x        = (const float*)d_in[0];
    const void*  ei       = d_in[1];
    const float* W        = (const float*)d_in[2];
    const float* att_src  = (const float*)d_in[3];
    const float* att_dst  = (const float*)d_in[4];
    const float* bias     = (const float*)d_in[5];
    const float* w1       = (const float*)d_in[6];
    const float* b1       = (const float*)d_in[7];
    const float* w2       = (const float*)d_in[8];
    const float* b2       = (const float*)d_in[9];
    float* out = (float*)d_out;

    int N = in_sizes[0] / 16;  // x is [N, 16]
    int E = in_sizes[1] / 2;   // edge_index is [2, E]
    int NB = (N + 1023) / 1024;          // 98 blocks <= 148 SMs (co-resident)
    int nodeBlocks = (N + 255) / 256;
    int packBlocks = (E + 255) / 256;

    k_init<<<1, 128>>>((const int*)ei);
    k_pack_node<<<nodeBlocks + packBlocks, 256>>>(ei, x, W, att_src, att_dst,
                                                  N, E, nodeBlocks);
    k_scan_scatter<<<NB, 1024>>>(N, E, NB);
    {
        long long T = (long long)N * 32;
        k2b3_aggregate<<<(unsigned)((T + 255) / 256), 256>>>(bias, w1, N);
    }
    k4_edge_mlp<<<1184, 256>>>(b1, w2, b2, out, E);
}

// round 14
// speedup vs baseline: 1.1325x; 1.1325x over previous
#include <cuda_runtime.h>
#include <cuda_fp16.h>

// Problem constants: N=100000, E=1600000, IN_C=16, HID=32, HEADS=2
#define MAXN 100000
#define MAXE 1600000
#define NEG 0.2f
#define INV_TEMP (1.0f / 0.7f)

// ---- device scratch (static; no allocations allowed) ----
__device__ __align__(16) __half g_xp[MAXN * 64];   // [N][64] projected features (fp16)
__device__ float g_asrc[MAXN * 2];                 // attention src logits per head
__device__ float g_adst[MAXN * 2];                 // attention dst logits per head
__device__ __align__(16) __half g_ps[MAXN * 32];   // h @ w1[0:32,:]  (fp16)
__device__ __align__(16) __half g_pd[MAXN * 32];   // h @ w1[32:64,:] (fp16)
__device__ __align__(16) int2 g_edge[MAXE];        // packed (src, dst)
__device__ __align__(16) int g_rank[MAXE];         // rank of edge within its dst group
__device__ __align__(16) int g_srcs[MAXE];         // CSR: src ids grouped by dst
__device__ int g_deg[MAXN];                        // in-degree histogram
__device__ int g_off[MAXN + 1];                    // CSR offsets
__device__ int g_bsum[128];                        // scan block totals
__device__ int g_bflag[128];                       // scan publish flags
__device__ int g_is64;

// K_init: zero histogram + scan flags; thread 0 detects edge int width
__global__ void k_init(const int* __restrict__ ei_words, int N) {
    int i = blockIdx.x * blockDim.x + threadIdx.x;
    if (i < N) g_deg[i] = 0;
    if (i < 128) g_bflag[i] = 0;
    if (i == 0) {
        int nonzero = 0;
        #pragma unroll
        for (int j = 0; j < 64; j++)
            if (ei_words[2 * j + 1] != 0) nonzero++;
        g_is64 = (nonzero == 0) ? 1 : 0;
    }
}

// K0b: pack edges to int2, build in-degree histogram, and record each edge's
// rank within its destination group (the atomicAdd return value — free).
__global__ void k0_pack(const void* __restrict__ ei, int E) {
    int e = blockIdx.x * blockDim.x + threadIdx.x;
    if (e >= E) return;
    int s, d;
    if (g_is64) {
        const long long* p = (const long long*)ei;
        s = (int)p[e];
        d = (int)p[e + E];
    } else {
        const int* p = (const int*)ei;
        s = p[e];
        d = p[e + E];
    }
    g_edge[e] = make_int2(s, d);
    g_rank[e] = atomicAdd(&g_deg[d], 1);
}

// K_scan: single-kernel exclusive scan of g_deg -> g_off (+ sentinel).
// Warp-shuffle block scan; cross-block base via parallel lookback (all <=98
// blocks co-resident, so the spin always progresses).
__global__ void __launch_bounds__(1024) k_scan(int N, int E) {
    __shared__ int warpsums[32];
    __shared__ int sred[32];
    __shared__ int sbase;
    const unsigned FULL = 0xFFFFFFFFu;
    int tid = threadIdx.x;
    int lane = tid & 31, wid = tid >> 5;
    int b = blockIdx.x;
    int i = b * 1024 + tid;

    int v = (i < N) ? g_deg[i] : 0;
    int sc = v;
    #pragma unroll
    for (int ofs = 1; ofs < 32; ofs <<= 1) {
        int t = __shfl_up_sync(FULL, sc, ofs);
        if (lane >= ofs) sc += t;
    }
    if (lane == 31) warpsums[wid] = sc;
    __syncthreads();
    if (wid == 0) {
        int w = warpsums[lane];
        #pragma unroll
        for (int ofs = 1; ofs < 32; ofs <<= 1) {
            int t = __shfl_up_sync(FULL, w, ofs);
            if (lane >= ofs) w += t;
        }
        warpsums[lane] = w;
    }
    __syncthreads();
    int blockpref = (wid > 0) ? warpsums[wid - 1] : 0;
    int excl = sc + blockpref - v;
    int total = warpsums[31];

    if (tid == 0) {
        g_bsum[b] = total;
        __threadfence();
        atomicExch(&g_bflag[b], 1);
    }

    int part = 0;
    if (tid < b) {
        while (atomicAdd(&g_bflag[tid], 0) == 0) { }
        __threadfence();
        part = g_bsum[tid];
    }
    #pragma unroll
    for (int ofs = 16; ofs > 0; ofs >>= 1)
        part += __shfl_xor_sync(FULL, part, ofs);
    if (lane == 0) sred[wid] = part;
    __syncthreads();
    if (tid == 0) {
        int s = 0;
        #pragma unroll
        for (int k = 0; k < 4; k++) s += sred[k];
        sbase = s;
    }
    __syncthreads();
    int base = sbase;

    if (i < N) g_off[i] = excl + base;
    if (b == 0 && tid == 0) g_off[N] = E;
}

// K_fused: blocks [0, nodeBlocks) do node projection (chunked, low-reg); the
// rest scatter edges WITHOUT atomics: pos = g_off[dst] + precomputed rank.
__global__ void __launch_bounds__(256, 4) k_fused_scatter_node(
    const float* __restrict__ x, const float* __restrict__ W,
    const float* __restrict__ att_src, const float* __restrict__ att_dst,
    int N, int E, int nodeBlocks) {
    int tid = threadIdx.x;

    if (blockIdx.x >= (unsigned)nodeBlocks) {
        // ---- edge scatter: 2 consecutive edges per thread, no atomics ----
        int e = ((blockIdx.x - nodeBlocks) * blockDim.x + tid) * 2;
        if (e >= E) return;
        if (e + 2 <= E) {
            int4 p01 = *(const int4*)(g_edge + e);   // (s0,d0,s1,d1)
            int2 r01 = *(const int2*)(g_rank + e);
            int o0 = __ldg(&g_off[p01.y]);
            int o1 = __ldg(&g_off[p01.w]);
            g_srcs[o0 + r01.x] = p01.x;
            g_srcs[o1 + r01.y] = p01.z;
        } else {
            int2 sd = g_edge[e];
            g_srcs[__ldg(&g_off[sd.y]) + g_rank[e]] = sd.x;
        }
        return;
    }

    // ---- node projection part (chunked, 16 output columns at a time) ----
    __shared__ float sW[16 * 64];
    __shared__ float sAs[64];
    __shared__ float sAd[64];
    for (int i = tid; i < 16 * 64; i += blockDim.x) sW[i] = W[i];
    if (tid < 64) { sAs[tid] = att_src[tid]; sAd[tid] = att_dst[tid]; }
    __syncthreads();

    int n = blockIdx.x * blockDim.x + tid;
    if (n >= N) return;

    float xv[16];
    const float4* x4 = (const float4*)(x + (size_t)n * 16);
    #pragma unroll
    for (int i = 0; i < 4; i++) {
        float4 t = x4[i];
        xv[4 * i + 0] = t.x; xv[4 * i + 1] = t.y;
        xv[4 * i + 2] = t.z; xv[4 * i + 3] = t.w;
    }

    float hs[2] = {0.f, 0.f};
    float hd[2] = {0.f, 0.f};
    uint4* xpo = (uint4*)(g_xp + (size_t)n * 64);

    #pragma unroll
    for (int ch = 0; ch < 4; ch++) {
        float v[16];
        float as = 0.f, ad = 0.f;
        #pragma unroll
        for (int jj = 0; jj < 16; jj++) {
            int j = ch * 16 + jj;
            float acc = 0.f;
            #pragma unroll
            for (int k = 0; k < 16; k++) acc = fmaf(xv[k], sW[k * 64 + j], acc);
            v[jj] = acc;
            as = fmaf(sAs[j], acc, as);
            ad = fmaf(sAd[j], acc, ad);
        }
        int hh = ch >> 1;
        hs[hh] += as;
        hd[hh] += ad;
        union { uint4 u; __half2 p[4]; } pk;
        #pragma unroll
        for (int g = 0; g < 2; g++) {
            #pragma unroll
            for (int j = 0; j < 4; j++)
                pk.p[j] = __floats2half2_rn(v[8 * g + 2 * j], v[8 * g + 2 * j + 1]);
            xpo[2 * ch + g] = pk.u;
        }
    }

    g_asrc[n * 2 + 0] = hs[0]; g_asrc[n * 2 + 1] = hs[1];
    g_adst[n * 2 + 0] = hd[0]; g_adst[n * 2 + 1] = hd[1];
}

// K2b3: warp-per-destination GAT aggregation + fused MLP layer-1 fold.
// Warp-COOPERATIVE weight computation: per 8-edge batch, lane l loads
// src[i+(l&7)] once; lanes 0..15 compute the 16 exp-weights (8 edges x 2
// heads); src ids and weights are distributed by shfl. 1 MUFU per batch
// instead of 8; 2 LDG per batch for ids/logits instead of 16.
__global__ void __launch_bounds__(256) k2b3_aggregate(const float* __restrict__ bias,
                                                      const float* __restrict__ w1, int N) {
    __shared__ float sW1[64 * 32];
    int tid = threadIdx.x;
    for (int i = tid; i < 64 * 32; i += blockDim.x) sW1[i] = w1[i];
    __syncthreads();

    int n = (blockIdx.x * blockDim.x + tid) >> 5;
    if (n >= N) return;
    int c = tid & 31;
    int h = c >> 4;
    const unsigned FULL = 0xFFFFFFFFu;

    float2 adn2 = *(const float2*)(g_adst + 2 * n);
    float adn = h ? adn2.y : adn2.x;

    // self loop
    float ee = g_asrc[n * 2 + h] + adn;
    ee = ee > 0.f ? ee : NEG * ee;
    float w = __expf(ee);
    float2 xs = __half22float2(*(const __half2*)(g_xp + (size_t)n * 64 + 2 * c));
    float acc0 = w * xs.x, acc1 = w * xs.y, dsum = w;

    int i = g_off[n];
    int end = g_off[n + 1];

    int js = c & 7;                 // which edge of the batch this lane owns
    int hh = (c >> 3) & 1;          // which head this lane computes
    float adnl = hh ? adn2.y : adn2.x;

    for (; i + 8 <= end; i += 8) {
        // one gather: lane l loads src id of edge (l&7)
        int s_my = __ldg(&g_srcs[i + js]);
        // lanes (j) / (j+8) hold head0 / head1 weights of edge j
        float aa = __ldg(&g_asrc[s_my * 2 + hh]);
        float el = aa + adnl;
        el = el > 0.f ? el : NEG * el;
        float wl = __expf(el);

        __half2 xh[8];
        #pragma unroll
        for (int j = 0; j < 8; j++) {
            int sj = __shfl_sync(FULL, s_my, j);
            xh[j] = *(const __half2*)(g_xp + (size_t)sj * 64 + 2 * c);
        }
        #pragma unroll
        for (int j = 0; j < 8; j++) {
            float w0 = __shfl_sync(FULL, wl, j + (h << 3));
            dsum += w0;
            float2 f = __half22float2(xh[j]);
            acc0 = fmaf(w0, f.x, acc0);
            acc1 = fmaf(w0, f.y, acc1);
        }
    }
    for (; i < end; i++) {
        int s = __ldg(&g_srcs[i]);
        float a = __ldg(&g_asrc[s * 2 + h]);
        __half2 xh = *(const __half2*)(g_xp + (size_t)s * 64 + 2 * c);
        float e0 = a + adn; e0 = e0 > 0.f ? e0 : NEG * e0;
        float w0 = __expf(e0);
        dsum += w0;
        float2 f = __half22float2(xh);
        acc0 = fmaf(w0, f.x, acc0);
        acc1 = fmaf(w0, f.y, acc1);
    }

    float d0 = __shfl_sync(FULL, dsum, 0);
    float d1 = __shfl_sync(FULL, dsum, 16);
    float p0 = __shfl_sync(FULL, acc0, (c + 16) & 31);
    float p1 = __shfl_sync(FULL, acc1, (c + 16) & 31);

    int c15 = c & 15;
    float h0 = 0.5f * (acc0 / d0 + p0 / d1) + __ldg(&bias[2 * c15]);
    float h1 = 0.5f * (acc1 / d0 + p1 / d1) + __ldg(&bias[2 * c15 + 1]);

    // fused k3: ps/pd = h @ w1 (lane c computes output channel c)
    float ps = 0.f, pd = 0.f;
    #pragma unroll
    for (int k = 0; k < 16; k++) {
        float ha = __shfl_sync(FULL, h0, k);
        float hb = __shfl_sync(FULL, h1, k);
        ps = fmaf(ha, sW1[(2 * k) * 32 + c], ps);
        ps = fmaf(hb, sW1[(2 * k + 1) * 32 + c], ps);
        pd = fmaf(ha, sW1[(32 + 2 * k) * 32 + c], pd);
        pd = fmaf(hb, sW1[(32 + 2 * k + 1) * 32 + c], pd);
    }
    g_ps[(size_t)n * 32 + c] = __float2half_rn(ps);
    g_pd[(size_t)n * 32 + c] = __float2half_rn(pd);
}

// K4: per-edge MLP. 4-lane group per consecutive edge pair (one int4 edge
// load); two independent pairs in flight per thread. ps+pd summed in half2.
__device__ __forceinline__ float mlp_quarter(const uint4 a, const uint4 b,
                                             const float* b1r, const float* w2r) {
    union { uint4 u; __half2 hh[4]; } ua, ub;
    ua.u = a; ub.u = b;
    float acc = 0.f;
    #pragma unroll
    for (int j = 0; j < 4; j++) {
        __half2 s = __hadd2(ua.hh[j], ub.hh[j]);
        float2 f = __half22float2(s);
        float h0 = fmaxf(f.x + b1r[2 * j], 0.f);
        float h1 = fmaxf(f.y + b1r[2 * j + 1], 0.f);
        acc = fmaf(h0, w2r[2 * j], acc);
        acc = fmaf(h1, w2r[2 * j + 1], acc);
    }
    return acc;
}

__global__ void __launch_bounds__(256) k4_edge_mlp(const float* __restrict__ b1,
                                                   const float* __restrict__ w2,
                                                   const float* __restrict__ b2,
                                                   float* __restrict__ out, int E) {
    int tid = blockIdx.x * blockDim.x + threadIdx.x;
    int q = tid & 3;
    float b1r[8], w2r[8];
    #pragma unroll
    for (int i = 0; i < 8; i++) {
        b1r[i] = __ldg(&b1[q * 8 + i]);
        w2r[i] = __ldg(&w2[q * 8 + i]);
    }
    float b2v = __ldg(&b2[0]);
    const unsigned FULL = 0xFFFFFFFFu;

    int nGroups = (gridDim.x * blockDim.x) >> 2;
    int nPairs = (E + 1) >> 1;

    for (int p = tid >> 2; p < nPairs; p += 2 * nGroups) {
        int pB = p + nGroups;
        bool hasB = pB < nPairs;
        int eA = 2 * p, eB = 2 * pB;

        int4 edA = __ldg((const int4*)(g_edge + eA));
        int4 edB = hasB ? __ldg((const int4*)(g_edge + eB)) : make_int4(0, 0, 0, 0);

        uint4 psA0 = *((const uint4*)(g_ps + (size_t)edA.x * 32) + q);
        uint4 pdA0 = *((const uint4*)(g_pd + (size_t)edA.y * 32) + q);
        uint4 psA1 = *((const uint4*)(g_ps + (size_t)edA.z * 32) + q);
        uint4 pdA1 = *((const uint4*)(g_pd + (size_t)edA.w * 32) + q);
        uint4 psB0 = *((const uint4*)(g_ps + (size_t)edB.x * 32) + q);
        uint4 pdB0 = *((const uint4*)(g_pd + (size_t)edB.y * 32) + q);
        uint4 psB1 = *((const uint4*)(g_ps + (size_t)edB.z * 32) + q);
        uint4 pdB1 = *((const uint4*)(g_pd + (size_t)edB.w * 32) + q);

        float vA0 = mlp_quarter(psA0, pdA0, b1r, w2r);
        float vA1 = mlp_quarter(psA1, pdA1, b1r, w2r);
        float vB0 = mlp_quarter(psB0, pdB0, b1r, w2r);
        float vB1 = mlp_quarter(psB1, pdB1, b1r, w2r);

        float a0 = vA0 + __shfl_xor_sync(FULL, vA0, 1);
        float a1 = vA1 + __shfl_xor_sync(FULL, vA1, 1);
        float mA = (q & 1) ? a1 : a0;
        mA += __shfl_xor_sync(FULL, mA, 2);

        float c0 = vB0 + __shfl_xor_sync(FULL, vB0, 1);
        float c1 = vB1 + __shfl_xor_sync(FULL, vB1, 1);
        float mB = (q & 1) ? c1 : c0;
        mB += __shfl_xor_sync(FULL, mB, 2);

        if (q < 2) {
            int e = eA + q;
            if (e < E) out[e] = (mA + b2v) * INV_TEMP;
            if (hasB) {
                int e2 = eB + q;
                if (e2 < E) out[e2] = (mB + b2v) * INV_TEMP;
            }
        }
    }
}

extern "C" void kernel_launch(void* const* d_in, const int* in_sizes, int n_in,
                              void* d_out, int out_size) {
    const float* x        = (const float*)d_in[0];
    const void*  ei       = d_in[1];
    const float* W        = (const float*)d_in[2];
    const float* att_src  = (const float*)d_in[3];
    const float* att_dst  = (const float*)d_in[4];
    const float* bias     = (const float*)d_in[5];
    const float* w1       = (const float*)d_in[6];
    const float* b1       = (const float*)d_in[7];
    const float* w2       = (const float*)d_in[8];
    const float* b2       = (const float*)d_in[9];
    float* out = (float*)d_out;

    int N = in_sizes[0] / 16;  // x is [N, 16]
    int E = in_sizes[1] / 2;   // edge_index is [2, E]
    int NB = (N + 1023) / 1024;
    int nodeBlocks = (N + 255) / 256;
    int edgeBlocks2 = (E + 511) / 512;   // 2 edges per thread in scatter

    k_init<<<(N + 255) / 256, 256>>>((const int*)ei, N);
    k0_pack<<<(E + 255) / 256, 256>>>(ei, E);
    k_scan<<<NB, 1024>>>(N, E);
    k_fused_scatter_node<<<nodeBlocks + edgeBlocks2, 256>>>(x, W, att_src, att_dst,
                                                            N, E, nodeBlocks);
    {
        long long T = (long long)N * 32;
        k2b3_aggregate<<<(unsigned)((T + 255) / 256), 256>>>(bias, w1, N);
    }
    k4_edge_mlp<<<1184, 256>>>(b1, w2, b2, out, E);
}

// round 15
// speedup vs baseline: 1.2434x; 1.0980x over previous
#include <cuda_runtime.h>
#include <cuda_fp16.h>

// Problem constants: N=100000, E=1600000, IN_C=16, HID=32, HEADS=2
#define MAXN 100000
#define MAXE 1600000
#define NEG 0.2f
#define INV_TEMP (1.0f / 0.7f)

// ---- device scratch (static; no allocations allowed) ----
__device__ __align__(16) __half g_xp[MAXN * 64];   // [N][64] projected features (fp16)
__device__ __align__(16) float g_asrc[MAXN * 2];   // attention src logits per head
__device__ __align__(16) float g_adst[MAXN * 2];   // attention dst logits per head
__device__ __align__(16) __half g_ps[MAXN * 32];   // h @ w1[0:32,:]  (fp16)
__device__ __align__(16) __half g_pd[MAXN * 32];   // h @ w1[32:64,:] (fp16)
__device__ __align__(16) int2 g_edge[MAXE];        // packed (src, dst)
__device__ __align__(16) int g_rank[MAXE];         // rank of edge within its dst group
__device__ __align__(16) int g_srcs[MAXE];         // CSR: src ids grouped by dst
__device__ int g_deg[MAXN];                        // in-degree histogram
__device__ int g_off[MAXN + 1];                    // CSR offsets
__device__ int g_bsum[128];                        // scan block totals
__device__ int g_bflag[128];                       // scan publish flags
__device__ int g_is64;

// K_init: zero histogram + scan flags; thread 0 detects edge int width
__global__ void k_init(const int* __restrict__ ei_words, int N) {
    int i = blockIdx.x * blockDim.x + threadIdx.x;
    if (i < N) g_deg[i] = 0;
    if (i < 128) g_bflag[i] = 0;
    if (i == 0) {
        int nonzero = 0;
        #pragma unroll
        for (int j = 0; j < 64; j++)
            if (ei_words[2 * j + 1] != 0) nonzero++;
        g_is64 = (nonzero == 0) ? 1 : 0;
    }
}

// K0b: pack edges to int2, build in-degree histogram, record per-dst rank.
__global__ void k0_pack(const void* __restrict__ ei, int E) {
    int e = blockIdx.x * blockDim.x + threadIdx.x;
    if (e >= E) return;
    int s, d;
    if (g_is64) {
        const long long* p = (const long long*)ei;
        s = (int)p[e];
        d = (int)p[e + E];
    } else {
        const int* p = (const int*)ei;
        s = p[e];
        d = p[e + E];
    }
    g_edge[e] = make_int2(s, d);
    g_rank[e] = atomicAdd(&g_deg[d], 1);
}

// K_scan: single-kernel exclusive scan of g_deg -> g_off (+ sentinel).
__global__ void __launch_bounds__(1024) k_scan(int N, int E) {
    __shared__ int warpsums[32];
    __shared__ int sred[32];
    __shared__ int sbase;
    const unsigned FULL = 0xFFFFFFFFu;
    int tid = threadIdx.x;
    int lane = tid & 31, wid = tid >> 5;
    int b = blockIdx.x;
    int i = b * 1024 + tid;

    int v = (i < N) ? g_deg[i] : 0;
    int sc = v;
    #pragma unroll
    for (int ofs = 1; ofs < 32; ofs <<= 1) {
        int t = __shfl_up_sync(FULL, sc, ofs);
        if (lane >= ofs) sc += t;
    }
    if (lane == 31) warpsums[wid] = sc;
    __syncthreads();
    if (wid == 0) {
        int w = warpsums[lane];
        #pragma unroll
        for (int ofs = 1; ofs < 32; ofs <<= 1) {
            int t = __shfl_up_sync(FULL, w, ofs);
            if (lane >= ofs) w += t;
        }
        warpsums[lane] = w;
    }
    __syncthreads();
    int blockpref = (wid > 0) ? warpsums[wid - 1] : 0;
    int excl = sc + blockpref - v;
    int total = warpsums[31];

    if (tid == 0) {
        g_bsum[b] = total;
        __threadfence();
        atomicExch(&g_bflag[b], 1);
    }

    int part = 0;
    if (tid < b) {
        while (atomicAdd(&g_bflag[tid], 0) == 0) { }
        __threadfence();
        part = g_bsum[tid];
    }
    #pragma unroll
    for (int ofs = 16; ofs > 0; ofs >>= 1)
        part += __shfl_xor_sync(FULL, part, ofs);
    if (lane == 0) sred[wid] = part;
    __syncthreads();
    if (tid == 0) {
        int s = 0;
        #pragma unroll
        for (int k = 0; k < 4; k++) s += sred[k];
        sbase = s;
    }
    __syncthreads();
    int base = sbase;

    if (i < N) g_off[i] = excl + base;
    if (b == 0 && tid == 0) g_off[N] = E;
}

// K_fused: blocks [0, nodeBlocks) do node projection (chunked, low-reg); the
// rest scatter edges WITHOUT atomics: pos = g_off[dst] + precomputed rank.
__global__ void __launch_bounds__(256, 4) k_fused_scatter_node(
    const float* __restrict__ x, const float* __restrict__ W,
    const float* __restrict__ att_src, const float* __restrict__ att_dst,
    int N, int E, int nodeBlocks) {
    int tid = threadIdx.x;

    if (blockIdx.x >= (unsigned)nodeBlocks) {
        int e = ((blockIdx.x - nodeBlocks) * blockDim.x + tid) * 2;
        if (e >= E) return;
        if (e + 2 <= E) {
            int4 p01 = *(const int4*)(g_edge + e);   // (s0,d0,s1,d1)
            int2 r01 = *(const int2*)(g_rank + e);
            int o0 = __ldg(&g_off[p01.y]);
            int o1 = __ldg(&g_off[p01.w]);
            g_srcs[o0 + r01.x] = p01.x;
            g_srcs[o1 + r01.y] = p01.z;
        } else {
            int2 sd = g_edge[e];
            g_srcs[__ldg(&g_off[sd.y]) + g_rank[e]] = sd.x;
        }
        return;
    }

    __shared__ float sW[16 * 64];
    __shared__ float sAs[64];
    __shared__ float sAd[64];
    for (int i = tid; i < 16 * 64; i += blockDim.x) sW[i] = W[i];
    if (tid < 64) { sAs[tid] = att_src[tid]; sAd[tid] = att_dst[tid]; }
    __syncthreads();

    int n = blockIdx.x * blockDim.x + tid;
    if (n >= N) return;

    float xv[16];
    const float4* x4 = (const float4*)(x + (size_t)n * 16);
    #pragma unroll
    for (int i = 0; i < 4; i++) {
        float4 t = x4[i];
        xv[4 * i + 0] = t.x; xv[4 * i + 1] = t.y;
        xv[4 * i + 2] = t.z; xv[4 * i + 3] = t.w;
    }

    float hs[2] = {0.f, 0.f};
    float hd[2] = {0.f, 0.f};
    uint4* xpo = (uint4*)(g_xp + (size_t)n * 64);

    #pragma unroll
    for (int ch = 0; ch < 4; ch++) {
        float v[16];
        float as = 0.f, ad = 0.f;
        #pragma unroll
        for (int jj = 0; jj < 16; jj++) {
            int j = ch * 16 + jj;
            float acc = 0.f;
            #pragma unroll
            for (int k = 0; k < 16; k++) acc = fmaf(xv[k], sW[k * 64 + j], acc);
            v[jj] = acc;
            as = fmaf(sAs[j], acc, as);
            ad = fmaf(sAd[j], acc, ad);
        }
        int hh = ch >> 1;
        hs[hh] += as;
        hd[hh] += ad;
        union { uint4 u; __half2 p[4]; } pk;
        #pragma unroll
        for (int g = 0; g < 2; g++) {
            #pragma unroll
            for (int j = 0; j < 4; j++)
                pk.p[j] = __floats2half2_rn(v[8 * g + 2 * j], v[8 * g + 2 * j + 1]);
            xpo[2 * ch + g] = pk.u;
        }
    }

    g_asrc[n * 2 + 0] = hs[0]; g_asrc[n * 2 + 1] = hs[1];
    g_adst[n * 2 + 0] = hd[0]; g_adst[n * 2 + 1] = hd[1];
}

// K2b3 v2: warp-per-destination GAT aggregation + fused MLP layer-1 fold.
// 2 EDGES PER ITERATION, 16 lanes per edge, 8 bytes (4 fp16 channels) per
// lane. Lane l: slot = l>>4 (edge of the pair), u = l&15 (byte offset u*8
// within the 128B xp row -> head = u>>3, channels 4*(u&7)..+3 of that head).
// Per-edge scalars (src id, logit, exp) are SIMT-shared across the 16 lanes.
__global__ void __launch_bounds__(256) k2b3_aggregate(const float* __restrict__ bias,
                                                      const float* __restrict__ w1, int N) {
    __shared__ float sW1[64 * 32];
    int tid = threadIdx.x;
    for (int i = tid; i < 64 * 32; i += blockDim.x) sW1[i] = w1[i];
    __syncthreads();

    int n = (blockIdx.x * blockDim.x + tid) >> 5;
    if (n >= N) return;
    int l = tid & 31;
    int slot = l >> 4;
    int u = l & 15;
    int head = u >> 3;
    const unsigned FULL = 0xFFFFFFFFu;

    float2 adn2 = *(const float2*)(g_adst + 2 * n);
    float adn = head ? adn2.y : adn2.x;

    // self loop (slot 0 lanes only, to avoid double count after slot-combine)
    float2 as2 = *(const float2*)(g_asrc + 2 * n);
    float aself = head ? as2.y : as2.x;
    float es = aself + adn; es = es > 0.f ? es : NEG * es;
    float wself = (slot == 0) ? __expf(es) : 0.f;
    uint2 xsv = *(const uint2*)((const char*)(g_xp + (size_t)n * 64) + u * 8);
    float2 sf0 = __half22float2(*(__half2*)&xsv.x);
    float2 sf1 = __half22float2(*(__half2*)&xsv.y);
    float acc0 = wself * sf0.x, acc1 = wself * sf0.y;
    float acc2 = wself * sf1.x, acc3 = wself * sf1.y;
    float dsum = wself;

    int i = g_off[n];
    int end = g_off[n + 1];

    // 4 edges per iteration: two independent 2-edge groups
    for (; i + 4 <= end; i += 4) {
        int sA = __ldg(&g_srcs[i + slot]);
        int sB = __ldg(&g_srcs[i + 2 + slot]);
        float aA = __ldg(&g_asrc[sA * 2 + head]);
        float aB = __ldg(&g_asrc[sB * 2 + head]);
        uint2 xvA = *(const uint2*)((const char*)(g_xp + (size_t)sA * 64) + u * 8);
        uint2 xvB = *(const uint2*)((const char*)(g_xp + (size_t)sB * 64) + u * 8);

        float eA = aA + adn; eA = eA > 0.f ? eA : NEG * eA;
        float eB = aB + adn; eB = eB > 0.f ? eB : NEG * eB;
        float wA = __expf(eA), wB = __expf(eB);
        dsum += wA + wB;

        float2 fA0 = __half22float2(*(__half2*)&xvA.x);
        float2 fA1 = __half22float2(*(__half2*)&xvA.y);
        float2 fB0 = __half22float2(*(__half2*)&xvB.x);
        float2 fB1 = __half22float2(*(__half2*)&xvB.y);
        acc0 = fmaf(wA, fA0.x, acc0); acc1 = fmaf(wA, fA0.y, acc1);
        acc2 = fmaf(wA, fA1.x, acc2); acc3 = fmaf(wA, fA1.y, acc3);
        acc0 = fmaf(wB, fB0.x, acc0); acc1 = fmaf(wB, fB0.y, acc1);
        acc2 = fmaf(wB, fB1.x, acc2); acc3 = fmaf(wB, fB1.y, acc3);
    }
    // 2-edge step
    if (i + 2 <= end) {
        int s = __ldg(&g_srcs[i + slot]);
        float a = __ldg(&g_asrc[s * 2 + head]);
        uint2 xv = *(const uint2*)((const char*)(g_xp + (size_t)s * 64) + u * 8);
        float e = a + adn; e = e > 0.f ? e : NEG * e;
        float w = __expf(e);
        dsum += w;
        float2 f0 = __half22float2(*(__half2*)&xv.x);
        float2 f1 = __half22float2(*(__half2*)&xv.y);
        acc0 = fmaf(w, f0.x, acc0); acc1 = fmaf(w, f0.y, acc1);
        acc2 = fmaf(w, f1.x, acc2); acc3 = fmaf(w, f1.y, acc3);
        i += 2;
    }
    // tail single edge: slot-1 lanes contribute zero
    if (i < end) {
        int s = __ldg(&g_srcs[i]);
        float a = __ldg(&g_asrc[s * 2 + head]);
        uint2 xv = *(const uint2*)((const char*)(g_xp + (size_t)s * 64) + u * 8);
        float e = a + adn; e = e > 0.f ? e : NEG * e;
        float w = (slot == 0) ? __expf(e) : 0.f;
        dsum += w;
        float2 f0 = __half22float2(*(__half2*)&xv.x);
        float2 f1 = __half22float2(*(__half2*)&xv.y);
        acc0 = fmaf(w, f0.x, acc0); acc1 = fmaf(w, f0.y, acc1);
        acc2 = fmaf(w, f1.x, acc2); acc3 = fmaf(w, f1.y, acc3);
    }

    // combine the two edge slots
    acc0 += __shfl_xor_sync(FULL, acc0, 16);
    acc1 += __shfl_xor_sync(FULL, acc1, 16);
    acc2 += __shfl_xor_sync(FULL, acc2, 16);
    acc3 += __shfl_xor_sync(FULL, acc3, 16);
    dsum += __shfl_xor_sync(FULL, dsum, 16);

    // other head's accumulators for the same channel indices
    float od0 = __shfl_xor_sync(FULL, acc0, 8);
    float od1 = __shfl_xor_sync(FULL, acc1, 8);
    float od2 = __shfl_xor_sync(FULL, acc2, 8);
    float od3 = __shfl_xor_sync(FULL, acc3, 8);
    float odd = __shfl_xor_sync(FULL, dsum, 8);

    float inv_d = 1.0f / dsum;
    float inv_o = 1.0f / odd;
    int cg = u & 7;
    const float4 bb = *(const float4*)(bias + 4 * cg);
    // h channels 4cg..4cg+3 (head-mean); identical on lanes u and u^8
    float h0v = 0.5f * (acc0 * inv_d + od0 * inv_o) + bb.x;
    float h1v = 0.5f * (acc1 * inv_d + od1 * inv_o) + bb.y;
    float h2v = 0.5f * (acc2 * inv_d + od2 * inv_o) + bb.z;
    float h3v = 0.5f * (acc3 * inv_d + od3 * inv_o) + bb.w;

    // fused k3: lane l computes ps[l], pd[l]; h[k] lives at lane k>>2 comp k&3
    float ps = 0.f, pd = 0.f;
    #pragma unroll
    for (int k = 0; k < 32; k += 4) {
        int srcl = k >> 2;
        float hk0 = __shfl_sync(FULL, h0v, srcl);
        float hk1 = __shfl_sync(FULL, h1v, srcl);
        float hk2 = __shfl_sync(FULL, h2v, srcl);
        float hk3 = __shfl_sync(FULL, h3v, srcl);
        ps = fmaf(hk0, sW1[(k + 0) * 32 + l], ps);
        ps = fmaf(hk1, sW1[(k + 1) * 32 + l], ps);
        ps = fmaf(hk2, sW1[(k + 2) * 32 + l], ps);
        ps = fmaf(hk3, sW1[(k + 3) * 32 + l], ps);
        pd = fmaf(hk0, sW1[(32 + k + 0) * 32 + l], pd);
        pd = fmaf(hk1, sW1[(32 + k + 1) * 32 + l], pd);
        pd = fmaf(hk2, sW1[(32 + k + 2) * 32 + l], pd);
        pd = fmaf(hk3, sW1[(32 + k + 3) * 32 + l], pd);
    }
    g_ps[(size_t)n * 32 + l] = __float2half_rn(ps);
    g_pd[(size_t)n * 32 + l] = __float2half_rn(pd);
}

// K4: per-edge MLP. 4-lane group per consecutive edge pair (one int4 edge
// load); two independent pairs in flight per thread. ps+pd summed in half2.
__device__ __forceinline__ float mlp_quarter(const uint4 a, const uint4 b,
                                             const float* b1r, const float* w2r) {
    union { uint4 u; __half2 hh[4]; } ua, ub;
    ua.u = a; ub.u = b;
    float acc = 0.f;
    #pragma unroll
    for (int j = 0; j < 4; j++) {
        __half2 s = __hadd2(ua.hh[j], ub.hh[j]);
        float2 f = __half22float2(s);
        float h0 = fmaxf(f.x + b1r[2 * j], 0.f);
        float h1 = fmaxf(f.y + b1r[2 * j + 1], 0.f);
        acc = fmaf(h0, w2r[2 * j], acc);
        acc = fmaf(h1, w2r[2 * j + 1], acc);
    }
    return acc;
}

__global__ void __launch_bounds__(256) k4_edge_mlp(const float* __restrict__ b1,
                                                   const float* __restrict__ w2,
                                                   const float* __restrict__ b2,
                                                   float* __restrict__ out, int E) {
    int tid = blockIdx.x * blockDim.x + threadIdx.x;
    int q = tid & 3;
    float b1r[8], w2r[8];
    #pragma unroll
    for (int i = 0; i < 8; i++) {
        b1r[i] = __ldg(&b1[q * 8 + i]);
        w2r[i] = __ldg(&w2[q * 8 + i]);
    }
    float b2v = __ldg(&b2[0]);
    const unsigned FULL = 0xFFFFFFFFu;

    int nGroups = (gridDim.x * blockDim.x) >> 2;
    int nPairs = (E + 1) >> 1;

    for (int p = tid >> 2; p < nPairs; p += 2 * nGroups) {
        int pB = p + nGroups;
        bool hasB = pB < nPairs;
        int eA = 2 * p, eB = 2 * pB;

        int4 edA = __ldg((const int4*)(g_edge + eA));
        int4 edB = hasB ? __ldg((const int4*)(g_edge + eB)) : make_int4(0, 0, 0, 0);

        uint4 psA0 = *((const uint4*)(g_ps + (size_t)edA.x * 32) + q);
        uint4 pdA0 = *((const uint4*)(g_pd + (size_t)edA.y * 32) + q);
        uint4 psA1 = *((const uint4*)(g_ps + (size_t)edA.z * 32) + q);
        uint4 pdA1 = *((const uint4*)(g_pd + (size_t)edA.w * 32) + q);
        uint4 psB0 = *((const uint4*)(g_ps + (size_t)edB.x * 32) + q);
        uint4 pdB0 = *((const uint4*)(g_pd + (size_t)edB.y * 32) + q);
        uint4 psB1 = *((const uint4*)(g_ps + (size_t)edB.z * 32) + q);
        uint4 pdB1 = *((const uint4*)(g_pd + (size_t)edB.w * 32) + q);

        float vA0 = mlp_quarter(psA0, pdA0, b1r, w2r);
        float vA1 = mlp_quarter(psA1, pdA1, b1r, w2r);
        float vB0 = mlp_quarter(psB0, pdB0, b1r, w2r);
        float vB1 = mlp_quarter(psB1, pdB1, b1r, w2r);

        float a0 = vA0 + __shfl_xor_sync(FULL, vA0, 1);
        float a1 = vA1 + __shfl_xor_sync(FULL, vA1, 1);
        float mA = (q & 1) ? a1 : a0;
        mA += __shfl_xor_sync(FULL, mA, 2);

        float c0 = vB0 + __shfl_xor_sync(FULL, vB0, 1);
        float c1 = vB1 + __shfl_xor_sync(FULL, vB1, 1);
        float mB = (q & 1) ? c1 : c0;
        mB += __shfl_xor_sync(FULL, mB, 2);

        if (q < 2) {
            int e = eA + q;
            if (e < E) out[e] = (mA + b2v) * INV_TEMP;
            if (hasB) {
                int e2 = eB + q;
                if (e2 < E) out[e2] = (mB + b2v) * INV_TEMP;
            }
        }
    }
}

extern "C" void kernel_launch(void* const* d_in, const int* in_sizes, int n_in,
                              void* d_out, int out_size) {
    const float* x        = (const float*)d_in[0];
    const void*  ei       = d_in[1];
    const float* W        = (const float*)d_in[2];
    const float* att_src  = (const float*)d_in[3];
    const float* att_dst  = (const float*)d_in[4];
    const float* bias     = (const float*)d_in[5];
    const float* w1       = (const float*)d_in[6];
    const float* b1       = (const float*)d_in[7];
    const float* w2       = (const float*)d_in[8];
    const float* b2       = (const float*)d_in[9];
    float* out = (float*)d_out;

    int N = in_sizes[0] / 16;  // x is [N, 16]
    int E = in_sizes[1] / 2;   // edge_index is [2, E]
    int NB = (N + 1023) / 1024;
    int nodeBlocks = (N + 255) / 256;
    int edgeBlocks2 = (E + 511) / 512;   // 2 edges per thread in scatter

    k_init<<<(N + 255) / 256, 256>>>((const int*)ei, N);
    k0_pack<<<(E + 255) / 256, 256>>>(ei, E);
    k_scan<<<NB, 1024>>>(N, E);
    k_fused_scatter_node<<<nodeBlocks + edgeBlocks2, 256>>>(x, W, att_src, att_dst,
                                                            N, E, nodeBlocks);
    {
        long long T = (long long)N * 32;
        k2b3_aggregate<<<(unsigned)((T + 255) / 256), 256>>>(bias, w1, N);
    }
    k4_edge_mlp<<<1184, 256>>>(b1, w2, b2, out, E);
}